// round 1
// baseline (speedup 1.0000x reference)
#include <cuda_runtime.h>

#define NT  8192
#define DIM 512
#define HID 2048
#define NE  4

// ---------------- device scratch (no allocs allowed) ----------------
__device__ int   g_cnt[NE];
__device__ int   g_tok[NE * NT];          // token id per (expert, slot)
__device__ int   g_slot[NT * 2];          // global slot id (e*NT+slot) per token per k
__device__ float g_gval[NT * 2];          // gate value per token per k
__device__ float g_mid[(size_t)NE * NT * HID];   // 256 MiB fp32 scratch
__device__ float g_y[(size_t)NE * NT * DIM];     // 64 MiB fp32 scratch

// ---------------- reset ----------------
__global__ void reset_kernel() {
    if (threadIdx.x < NE) g_cnt[threadIdx.x] = 0;
}

// ---------------- gating: warp per token ----------------
__global__ void gate_kernel(const float* __restrict__ h,
                            const float* __restrict__ wg) {
    int gw   = (blockIdx.x * blockDim.x + threadIdx.x) >> 5;
    int lane = threadIdx.x & 31;
    if (gw >= NT) return;
    const float* hr = h + (size_t)gw * DIM;
    float a0 = 0.f, a1 = 0.f, a2 = 0.f, a3 = 0.f;
    #pragma unroll
    for (int i = lane; i < DIM; i += 32) {
        float  hv = hr[i];
        float4 w  = reinterpret_cast<const float4*>(wg)[i];  // wg is [D,4] row-major
        a0 += hv * w.x; a1 += hv * w.y; a2 += hv * w.z; a3 += hv * w.w;
    }
    #pragma unroll
    for (int o = 16; o; o >>= 1) {
        a0 += __shfl_xor_sync(0xffffffffu, a0, o);
        a1 += __shfl_xor_sync(0xffffffffu, a1, o);
        a2 += __shfl_xor_sync(0xffffffffu, a2, o);
        a3 += __shfl_xor_sync(0xffffffffu, a3, o);
    }
    if (lane == 0) {
        float l[4] = {a0, a1, a2, a3};
        int i0 = 0;
        #pragma unroll
        for (int e = 1; e < 4; e++) if (l[e] > l[i0]) i0 = e;   // ties -> lower idx (matches top_k)
        int i1 = -1;
        #pragma unroll
        for (int e = 0; e < 4; e++)
            if (e != i0 && (i1 < 0 || l[e] > l[i1])) i1 = e;
        float p1  = expf(l[i1] - l[i0]);          // softmax over the two top logits
        float inv = 1.0f / (1.0f + p1);
        int p = atomicAdd(&g_cnt[i0], 1);
        g_tok[i0 * NT + p] = gw;
        g_slot[gw * 2]     = i0 * NT + p;
        g_gval[gw * 2]     = inv;                 // gate for max logit
        int q = atomicAdd(&g_cnt[i1], 1);
        g_tok[i1 * NT + q] = gw;
        g_slot[gw * 2 + 1] = i1 * NT + q;
        g_gval[gw * 2 + 1] = p1 * inv;            // gate for 2nd logit
    }
}

// ---------------- GEMM1: mid = relu(h[tok] @ W1[e] + b1[e]) ----------------
// grid: (HID/128, NT/128, NE), block: 256 threads, BM=BN=128, BK=16, 8x8/thread
__global__ __launch_bounds__(256) void ffn1_kernel(const float* __restrict__ h,
                                                   const float* __restrict__ w1,
                                                   const float* __restrict__ b1) {
    const int e   = blockIdx.z;
    const int cnt = g_cnt[e];
    const int m0  = blockIdx.y * 128;
    if (m0 >= cnt) return;
    const int n0  = blockIdx.x * 128;

    __shared__ float As[16][128];   // As[k][m]
    __shared__ float Bs[16][128];   // Bs[k][n]

    const int tid = threadIdx.x;
    // A loader: thread handles row lm, 8 contiguous k's starting at lkc*4
    const int lm  = tid >> 1;
    const int lkc = (tid & 1) * 2;
    int row = m0 + lm; if (row >= cnt) row = cnt - 1;       // clamp (store is guarded)
    const float* arow = h + (size_t)g_tok[e * NT + row] * DIM;
    // B loader: thread handles k=bk, 8 contiguous n's starting at bn4*4
    const int bk  = tid >> 4;
    const int bn4 = (tid & 15) * 2;
    const float* B = w1 + (size_t)e * DIM * HID;

    const int tm0 = (tid >> 4) << 3;
    const int tn0 = (tid & 15) << 3;

    float acc[64];
    #pragma unroll
    for (int i = 0; i < 64; i++) acc[i] = 0.f;

    for (int kt = 0; kt < DIM / 16; kt++) {
        const int k0 = kt * 16;
        float4 av0 = *reinterpret_cast<const float4*>(arow + k0 + lkc * 4);
        float4 av1 = *reinterpret_cast<const float4*>(arow + k0 + lkc * 4 + 4);
        float4 bv0 = *reinterpret_cast<const float4*>(B + (size_t)(k0 + bk) * HID + n0 + bn4 * 4);
        float4 bv1 = *reinterpret_cast<const float4*>(B + (size_t)(k0 + bk) * HID + n0 + bn4 * 4 + 4);
        __syncthreads();
        As[lkc * 4 + 0][lm] = av0.x; As[lkc * 4 + 1][lm] = av0.y;
        As[lkc * 4 + 2][lm] = av0.z; As[lkc * 4 + 3][lm] = av0.w;
        As[lkc * 4 + 4][lm] = av1.x; As[lkc * 4 + 5][lm] = av1.y;
        As[lkc * 4 + 6][lm] = av1.z; As[lkc * 4 + 7][lm] = av1.w;
        *reinterpret_cast<float4*>(&Bs[bk][bn4 * 4])     = bv0;
        *reinterpret_cast<float4*>(&Bs[bk][bn4 * 4 + 4]) = bv1;
        __syncthreads();
        #pragma unroll
        for (int k = 0; k < 16; k++) {
            float a[8], b[8];
            *reinterpret_cast<float4*>(a)     = *reinterpret_cast<const float4*>(&As[k][tm0]);
            *reinterpret_cast<float4*>(a + 4) = *reinterpret_cast<const float4*>(&As[k][tm0 + 4]);
            *reinterpret_cast<float4*>(b)     = *reinterpret_cast<const float4*>(&Bs[k][tn0]);
            *reinterpret_cast<float4*>(b + 4) = *reinterpret_cast<const float4*>(&Bs[k][tn0 + 4]);
            #pragma unroll
            for (int i = 0; i < 8; i++)
                #pragma unroll
                for (int j = 0; j < 8; j++)
                    acc[i * 8 + j] += a[i] * b[j];
        }
    }

    float4 b1v0 = *reinterpret_cast<const float4*>(b1 + e * HID + n0 + tn0);
    float4 b1v1 = *reinterpret_cast<const float4*>(b1 + e * HID + n0 + tn0 + 4);
    const float bb[8] = {b1v0.x, b1v0.y, b1v0.z, b1v0.w, b1v1.x, b1v1.y, b1v1.z, b1v1.w};
    #pragma unroll
    for (int i = 0; i < 8; i++) {
        int r = m0 + tm0 + i;
        if (r < cnt) {
            float* orow = g_mid + ((size_t)e * NT + r) * HID + n0 + tn0;
            float4 v0, v1;
            v0.x = fmaxf(acc[i * 8 + 0] + bb[0], 0.f);
            v0.y = fmaxf(acc[i * 8 + 1] + bb[1], 0.f);
            v0.z = fmaxf(acc[i * 8 + 2] + bb[2], 0.f);
            v0.w = fmaxf(acc[i * 8 + 3] + bb[3], 0.f);
            v1.x = fmaxf(acc[i * 8 + 4] + bb[4], 0.f);
            v1.y = fmaxf(acc[i * 8 + 5] + bb[5], 0.f);
            v1.z = fmaxf(acc[i * 8 + 6] + bb[6], 0.f);
            v1.w = fmaxf(acc[i * 8 + 7] + bb[7], 0.f);
            *reinterpret_cast<float4*>(orow)     = v0;
            *reinterpret_cast<float4*>(orow + 4) = v1;
        }
    }
}

// ---------------- GEMM2: y = mid @ W2[e] + b2[e] ----------------
// grid: (DIM/128, NT/128, NE)
__global__ __launch_bounds__(256) void ffn2_kernel(const float* __restrict__ w2,
                                                   const float* __restrict__ b2) {
    const int e   = blockIdx.z;
    const int cnt = g_cnt[e];
    const int m0  = blockIdx.y * 128;
    if (m0 >= cnt) return;
    const int n0  = blockIdx.x * 128;

    __shared__ float As[16][128];
    __shared__ float Bs[16][128];

    const int tid = threadIdx.x;
    const int lm  = tid >> 1;
    const int lkc = (tid & 1) * 2;
    int row = m0 + lm; if (row >= cnt) row = cnt - 1;
    const float* arow = g_mid + ((size_t)e * NT + row) * HID;
    const int bk  = tid >> 4;
    const int bn4 = (tid & 15) * 2;
    const float* B = w2 + (size_t)e * HID * DIM;

    const int tm0 = (tid >> 4) << 3;
    const int tn0 = (tid & 15) << 3;

    float acc[64];
    #pragma unroll
    for (int i = 0; i < 64; i++) acc[i] = 0.f;

    for (int kt = 0; kt < HID / 16; kt++) {
        const int k0 = kt * 16;
        float4 av0 = *reinterpret_cast<const float4*>(arow + k0 + lkc * 4);
        float4 av1 = *reinterpret_cast<const float4*>(arow + k0 + lkc * 4 + 4);
        float4 bv0 = *reinterpret_cast<const float4*>(B + (size_t)(k0 + bk) * DIM + n0 + bn4 * 4);
        float4 bv1 = *reinterpret_cast<const float4*>(B + (size_t)(k0 + bk) * DIM + n0 + bn4 * 4 + 4);
        __syncthreads();
        As[lkc * 4 + 0][lm] = av0.x; As[lkc * 4 + 1][lm] = av0.y;
        As[lkc * 4 + 2][lm] = av0.z; As[lkc * 4 + 3][lm] = av0.w;
        As[lkc * 4 + 4][lm] = av1.x; As[lkc * 4 + 5][lm] = av1.y;
        As[lkc * 4 + 6][lm] = av1.z; As[lkc * 4 + 7][lm] = av1.w;
        *reinterpret_cast<float4*>(&Bs[bk][bn4 * 4])     = bv0;
        *reinterpret_cast<float4*>(&Bs[bk][bn4 * 4 + 4]) = bv1;
        __syncthreads();
        #pragma unroll
        for (int k = 0; k < 16; k++) {
            float a[8], b[8];
            *reinterpret_cast<float4*>(a)     = *reinterpret_cast<const float4*>(&As[k][tm0]);
            *reinterpret_cast<float4*>(a + 4) = *reinterpret_cast<const float4*>(&As[k][tm0 + 4]);
            *reinterpret_cast<float4*>(b)     = *reinterpret_cast<const float4*>(&Bs[k][tn0]);
            *reinterpret_cast<float4*>(b + 4) = *reinterpret_cast<const float4*>(&Bs[k][tn0 + 4]);
            #pragma unroll
            for (int i = 0; i < 8; i++)
                #pragma unroll
                for (int j = 0; j < 8; j++)
                    acc[i * 8 + j] += a[i] * b[j];
        }
    }

    float4 b2v0 = *reinterpret_cast<const float4*>(b2 + e * DIM + n0 + tn0);
    float4 b2v1 = *reinterpret_cast<const float4*>(b2 + e * DIM + n0 + tn0 + 4);
    const float bb[8] = {b2v0.x, b2v0.y, b2v0.z, b2v0.w, b2v1.x, b2v1.y, b2v1.z, b2v1.w};
    #pragma unroll
    for (int i = 0; i < 8; i++) {
        int r = m0 + tm0 + i;
        if (r < cnt) {
            float* orow = g_y + ((size_t)e * NT + r) * DIM + n0 + tn0;
            float4 v0, v1;
            v0.x = acc[i * 8 + 0] + bb[0]; v0.y = acc[i * 8 + 1] + bb[1];
            v0.z = acc[i * 8 + 2] + bb[2]; v0.w = acc[i * 8 + 3] + bb[3];
            v1.x = acc[i * 8 + 4] + bb[4]; v1.y = acc[i * 8 + 5] + bb[5];
            v1.z = acc[i * 8 + 6] + bb[6]; v1.w = acc[i * 8 + 7] + bb[7];
            *reinterpret_cast<float4*>(orow)     = v0;
            *reinterpret_cast<float4*>(orow + 4) = v1;
        }
    }
}

// ---------------- combine: out[n] = gA*y[slotA] + gB*y[slotB] ----------------
__global__ void combine_kernel(float* __restrict__ out) {
    int idx = blockIdx.x * blockDim.x + threadIdx.x;       // over NT * DIM/4
    if (idx >= NT * (DIM / 4)) return;
    int n = idx / (DIM / 4);
    int c = idx % (DIM / 4);
    int   sA = g_slot[n * 2],     sB = g_slot[n * 2 + 1];
    float gA = g_gval[n * 2],     gB = g_gval[n * 2 + 1];
    const float4* y4 = reinterpret_cast<const float4*>(g_y);
    float4 a = y4[(size_t)sA * (DIM / 4) + c];
    float4 b = y4[(size_t)sB * (DIM / 4) + c];
    float4 o;
    o.x = gA * a.x + gB * b.x;
    o.y = gA * a.y + gB * b.y;
    o.z = gA * a.z + gB * b.z;
    o.w = gA * a.w + gB * b.w;
    reinterpret_cast<float4*>(out)[idx] = o;
}

// ---------------- launch ----------------
extern "C" void kernel_launch(void* const* d_in, const int* in_sizes, int n_in,
                              void* d_out, int out_size) {
    const float* h  = (const float*)d_in[0];   // [NT, DIM]
    const float* wg = (const float*)d_in[1];   // [DIM, NE]
    const float* w1 = (const float*)d_in[2];   // [NE, DIM, HID]
    const float* b1 = (const float*)d_in[3];   // [NE, HID]
    const float* w2 = (const float*)d_in[4];   // [NE, HID, DIM]
    const float* b2 = (const float*)d_in[5];   // [NE, DIM]
    float* out = (float*)d_out;                // [NT, DIM]

    reset_kernel<<<1, 32>>>();
    gate_kernel<<<(NT * 32) / 256, 256>>>(h, wg);
    dim3 g1(HID / 128, NT / 128, NE);
    ffn1_kernel<<<g1, 256>>>(h, w1, b1);
    dim3 g2(DIM / 128, NT / 128, NE);
    ffn2_kernel<<<g2, 256>>>(w2, b2);
    combine_kernel<<<(NT * (DIM / 4) + 255) / 256, 256>>>(out);
}

// round 7
// speedup vs baseline: 1.1665x; 1.1665x over previous
#include <cuda_runtime.h>
#include <cstdint>

#define NT  8192
#define DIM 512
#define HID 2048
#define NE  4
#define BM  128
#define BN  128
#define BK  16

// ---------------- device scratch (no allocs allowed) ----------------
__device__ __align__(16) int   g_cnt[NE];
__device__ __align__(16) int   g_tok[NE * NT];
__device__ __align__(16) int   g_slot[NT * 2];
__device__ __align__(16) float g_gval[NT * 2];
__device__ __align__(16) float g_mid[(size_t)NE * NT * HID];   // 256 MiB fp32
__device__ __align__(16) float g_y[(size_t)NE * NT * DIM];     // 64 MiB fp32

typedef unsigned long long ull;

// ---------------- packed f32x2 helpers (Blackwell base-arch PTX) ----------------
__device__ __forceinline__ void ffma2(ull& d, ull a, ull b) {
    asm("fma.rn.f32x2 %0, %1, %2, %0;" : "+l"(d) : "l"(a), "l"(b));
}
__device__ __forceinline__ ull bcast2(float x) {
    ull r; uint32_t u = __float_as_uint(x);
    asm("mov.b64 %0, {%1, %2};" : "=l"(r) : "r"(u), "r"(u));
    return r;
}
__device__ __forceinline__ float2 unpack2(ull p) {
    uint32_t lo, hi;
    asm("mov.b64 {%0, %1}, %2;" : "=r"(lo), "=r"(hi) : "l"(p));
    return make_float2(__uint_as_float(lo), __uint_as_float(hi));
}

// ---------------- reset ----------------
__global__ void reset_kernel() {
    if (threadIdx.x < NE) g_cnt[threadIdx.x] = 0;
}

// ---------------- gating: warp per token (proven R1) ----------------
__global__ void gate_kernel(const float* __restrict__ h,
                            const float* __restrict__ wg) {
    int gw   = (blockIdx.x * blockDim.x + threadIdx.x) >> 5;
    int lane = threadIdx.x & 31;
    if (gw >= NT) return;
    const float* hr = h + (size_t)gw * DIM;
    float a0 = 0.f, a1 = 0.f, a2 = 0.f, a3 = 0.f;
    for (int i = lane; i < DIM; i += 32) {
        float  hv = hr[i];
        float4 w  = reinterpret_cast<const float4*>(wg)[i];
        a0 += hv * w.x; a1 += hv * w.y; a2 += hv * w.z; a3 += hv * w.w;
    }
    #pragma unroll
    for (int o = 16; o; o >>= 1) {
        a0 += __shfl_xor_sync(0xffffffffu, a0, o);
        a1 += __shfl_xor_sync(0xffffffffu, a1, o);
        a2 += __shfl_xor_sync(0xffffffffu, a2, o);
        a3 += __shfl_xor_sync(0xffffffffu, a3, o);
    }
    if (lane == 0) {
        float l[4] = {a0, a1, a2, a3};
        int i0 = 0;
        #pragma unroll
        for (int e = 1; e < 4; e++) if (l[e] > l[i0]) i0 = e;
        int i1 = -1;
        #pragma unroll
        for (int e = 0; e < 4; e++)
            if (e != i0 && (i1 < 0 || l[e] > l[i1])) i1 = e;
        float p1  = expf(l[i1] - l[i0]);
        float inv = 1.0f / (1.0f + p1);
        int p = atomicAdd(&g_cnt[i0], 1);
        g_tok[i0 * NT + p] = gw;
        g_slot[gw * 2]     = i0 * NT + p;
        g_gval[gw * 2]     = inv;
        int q = atomicAdd(&g_cnt[i1], 1);
        g_tok[i1 * NT + q] = gw;
        g_slot[gw * 2 + 1] = i1 * NT + q;
        g_gval[gw * 2 + 1] = p1 * inv;
    }
}

// ---------------- grouped GEMM: f32x2 packed FFMA, double-buffered, pipelined ----------------
// D[128,128] = A[128,K] @ B[K,128] (+bias, opt relu). B is naturally [k][n] in gmem.
// 256 threads, 8x8 microtile per thread; acc packed in pairs along n:
//   thread covers rows tm0..tm0+7, col pairs {tnb+32q, tnb+32q+1}, q=0..3.
template<int KTOT, int NTOT, bool GATHER, bool RELU>
__global__ void __launch_bounds__(256) gemm_kernel(const float* __restrict__ Ain,
                                                   const float* __restrict__ Bg,
                                                   const float* __restrict__ bias) {
    const int e   = blockIdx.z;
    const int cnt = g_cnt[e];
    const int m0  = blockIdx.y * BM;
    if (m0 >= cnt) return;
    const int n0  = blockIdx.x * BN;

    const float* Ag = GATHER ? Ain : g_mid;     // template-const selection
    float* outp     = RELU ? g_mid : g_y;

    __shared__ float As[2][BK][BM];
    __shared__ float Bs[2][BK][BN];

    const int tid = threadIdx.x;

    // A loader: thread handles row lm, k's lk8..lk8+7 (2 x float4)
    const int lm  = tid >> 1, lk8 = (tid & 1) * 8;
    int arow = m0 + lm; if (arow >= cnt) arow = cnt - 1;
    const float* aptr;
    if (GATHER) aptr = Ag + (size_t)g_tok[e * NT + arow] * KTOT + lk8;
    else        aptr = Ag + ((size_t)e * NT + arow) * KTOT + lk8;

    // B loader: thread handles k-row bk, 2 x float4 at cols bc, bc+64
    const int bk = tid >> 4, bc = (tid & 15) * 4;
    const float* bptr = Bg + (size_t)e * KTOT * NTOT + (size_t)bk * NTOT + n0 + bc;

    const int tm0 = (tid >> 4) * 8;     // 2 distinct per warp -> broadcast A frags
    const int tnb = (tid & 15) * 2;     // LDS.64 stride 8B over 16 lanes -> conflict-free

    ull acc[8][4];
    #pragma unroll
    for (int i = 0; i < 8; i++)
        #pragma unroll
        for (int q = 0; q < 4; q++) acc[i][q] = 0ull;

    // prologue: tile 0 into regs
    float4 pa0 = *reinterpret_cast<const float4*>(aptr);
    float4 pa1 = *reinterpret_cast<const float4*>(aptr + 4);
    float4 pb0 = *reinterpret_cast<const float4*>(bptr);
    float4 pb1 = *reinterpret_cast<const float4*>(bptr + 64);

    const int KT = KTOT / BK;
    for (int kt = 0; kt < KT; kt++) {
        const int s = kt & 1;
        // stage tile kt into smem (A transposed to [k][m])
        As[s][lk8 + 0][lm] = pa0.x; As[s][lk8 + 1][lm] = pa0.y;
        As[s][lk8 + 2][lm] = pa0.z; As[s][lk8 + 3][lm] = pa0.w;
        As[s][lk8 + 4][lm] = pa1.x; As[s][lk8 + 5][lm] = pa1.y;
        As[s][lk8 + 6][lm] = pa1.z; As[s][lk8 + 7][lm] = pa1.w;
        *reinterpret_cast<float4*>(&Bs[s][bk][bc])      = pb0;
        *reinterpret_cast<float4*>(&Bs[s][bk][bc + 64]) = pb1;
        __syncthreads();

        // issue next tile's global loads before compute (latency hidden by MMAs)
        if (kt + 1 < KT) {
            const float* ap = aptr + (kt + 1) * BK;
            const float* bp = bptr + (size_t)(kt + 1) * BK * NTOT;
            pa0 = *reinterpret_cast<const float4*>(ap);
            pa1 = *reinterpret_cast<const float4*>(ap + 4);
            pb0 = *reinterpret_cast<const float4*>(bp);
            pb1 = *reinterpret_cast<const float4*>(bp + 64);
        }

        #pragma unroll
        for (int k = 0; k < BK; k++) {
            float4 a0 = *reinterpret_cast<const float4*>(&As[s][k][tm0]);
            float4 a1 = *reinterpret_cast<const float4*>(&As[s][k][tm0 + 4]);
            ull bv0 = *reinterpret_cast<const ull*>(&Bs[s][k][tnb]);
            ull bv1 = *reinterpret_cast<const ull*>(&Bs[s][k][tnb + 32]);
            ull bv2 = *reinterpret_cast<const ull*>(&Bs[s][k][tnb + 64]);
            ull bv3 = *reinterpret_cast<const ull*>(&Bs[s][k][tnb + 96]);
            ull av;
            av = bcast2(a0.x);
            ffma2(acc[0][0], av, bv0); ffma2(acc[0][1], av, bv1);
            ffma2(acc[0][2], av, bv2); ffma2(acc[0][3], av, bv3);
            av = bcast2(a0.y);
            ffma2(acc[1][0], av, bv0); ffma2(acc[1][1], av, bv1);
            ffma2(acc[1][2], av, bv2); ffma2(acc[1][3], av, bv3);
            av = bcast2(a0.z);
            ffma2(acc[2][0], av, bv0); ffma2(acc[2][1], av, bv1);
            ffma2(acc[2][2], av, bv2); ffma2(acc[2][3], av, bv3);
            av = bcast2(a0.w);
            ffma2(acc[3][0], av, bv0); ffma2(acc[3][1], av, bv1);
            ffma2(acc[3][2], av, bv2); ffma2(acc[3][3], av, bv3);
            av = bcast2(a1.x);
            ffma2(acc[4][0], av, bv0); ffma2(acc[4][1], av, bv1);
            ffma2(acc[4][2], av, bv2); ffma2(acc[4][3], av, bv3);
            av = bcast2(a1.y);
            ffma2(acc[5][0], av, bv0); ffma2(acc[5][1], av, bv1);
            ffma2(acc[5][2], av, bv2); ffma2(acc[5][3], av, bv3);
            av = bcast2(a1.z);
            ffma2(acc[6][0], av, bv0); ffma2(acc[6][1], av, bv1);
            ffma2(acc[6][2], av, bv2); ffma2(acc[6][3], av, bv3);
            av = bcast2(a1.w);
            ffma2(acc[7][0], av, bv0); ffma2(acc[7][1], av, bv1);
            ffma2(acc[7][2], av, bv2); ffma2(acc[7][3], av, bv3);
        }
        __syncthreads();
    }

    // ---- epilogue: bias (+relu), float2 stores ----
    #pragma unroll
    for (int i = 0; i < 8; i++) {
        const int r = m0 + tm0 + i;
        if (r < cnt) {
            float* orow = outp + ((size_t)e * NT + r) * NTOT + n0;
            #pragma unroll
            for (int q = 0; q < 4; q++) {
                const int c = tnb + 32 * q;
                float2 v = unpack2(acc[i][q]);
                v.x += bias[(size_t)e * NTOT + n0 + c];
                v.y += bias[(size_t)e * NTOT + n0 + c + 1];
                if (RELU) { v.x = fmaxf(v.x, 0.f); v.y = fmaxf(v.y, 0.f); }
                *reinterpret_cast<float2*>(orow + c) = v;
            }
        }
    }
}

// ---------------- combine (proven R1) ----------------
__global__ void combine_kernel(float* __restrict__ out) {
    int idx = blockIdx.x * blockDim.x + threadIdx.x;
    if (idx >= NT * (DIM / 4)) return;
    int n = idx / (DIM / 4);
    int c = idx % (DIM / 4);
    int   sA = g_slot[n * 2],     sB = g_slot[n * 2 + 1];
    float gA = g_gval[n * 2],     gB = g_gval[n * 2 + 1];
    const float4* y4 = reinterpret_cast<const float4*>(g_y);
    float4 a = y4[(size_t)sA * (DIM / 4) + c];
    float4 b = y4[(size_t)sB * (DIM / 4) + c];
    float4 o;
    o.x = gA * a.x + gB * b.x;
    o.y = gA * a.y + gB * b.y;
    o.z = gA * a.z + gB * b.z;
    o.w = gA * a.w + gB * b.w;
    reinterpret_cast<float4*>(out)[idx] = o;
}

// ---------------- launch ----------------
extern "C" void kernel_launch(void* const* d_in, const int* in_sizes, int n_in,
                              void* d_out, int out_size) {
    const float* h  = (const float*)d_in[0];   // [NT, DIM]
    const float* wg = (const float*)d_in[1];   // [DIM, NE]
    const float* w1 = (const float*)d_in[2];   // [NE, DIM, HID]  = [e][k][n]
    const float* b1 = (const float*)d_in[3];   // [NE, HID]
    const float* w2 = (const float*)d_in[4];   // [NE, HID, DIM]  = [e][k][n]
    const float* b2 = (const float*)d_in[5];   // [NE, DIM]
    float* out = (float*)d_out;                // [NT, DIM]

    reset_kernel<<<1, 32>>>();
    gate_kernel<<<(NT * 32) / 256, 256>>>(h, wg);
    {   // GEMM1: mid = relu(h[tok] @ w1[e] + b1)
        dim3 g(HID / BN, NT / BM, NE);
        gemm_kernel<DIM, HID, true, true><<<g, 256>>>(h, w1, b1);
    }
    {   // GEMM2: y = mid @ w2[e] + b2
        dim3 g(DIM / BN, NT / BM, NE);
        gemm_kernel<HID, DIM, false, false><<<g, 256>>>(h /*unused*/, w2, b2);
    }
    combine_kernel<<<(NT * (DIM / 4) + 255) / 256, 256>>>(out);
}